// round 12
// baseline (speedup 1.0000x reference)
#include <cuda_runtime.h>
#include <cuda_fp16.h>
#include <cstdint>

// ===================== problem constants =====================
#define DIMD 1024
#define BATCH 65536
#define NITERS 20

// sinkhorn config
#define NCTA_S 128
#define STHR 256
#define RPC 8               // rows per sinkhorn CTA (128*8 = 1024)

// ===================== device globals (static scratch; never allocated) =====================
__device__ __half  g_P[DIMD * DIMD];            // Sinkhorn P (row-major = K-major B operand)
__device__ float   g_colSum[NITERS][DIMD];      // per-iter column sums (atomic-accumulated)
__device__ unsigned g_bar;                      // monotonic grid barrier counter
__device__ unsigned g_done;                     // end-of-kernel reset rendezvous

// ===================== small PTX helpers (plain sm_103-legal only) =====================
__device__ __forceinline__ uint32_t smem_to_u32(const void* p) {
    uint32_t a;
    asm("{ .reg .u64 t; cvta.to.shared.u64 t, %1; cvt.u32.u64 %0, t; }" : "=r"(a) : "l"(p));
    return a;
}

#define CP_ASYNC16(dst, src) \
    asm volatile("cp.async.cg.shared.global [%0], [%1], 16;" :: "r"(dst), "l"(src) : "memory")
#define CP_ASYNC_COMMIT() asm volatile("cp.async.commit_group;" ::: "memory")
#define CP_ASYNC_WAIT1()  asm volatile("cp.async.wait_group 1;" ::: "memory")

__device__ __forceinline__ void ldsm_x4(uint32_t* r, uint32_t addr) {
    asm volatile("ldmatrix.sync.aligned.m8n8.x4.shared.b16 {%0,%1,%2,%3}, [%4];"
                 : "=r"(r[0]), "=r"(r[1]), "=r"(r[2]), "=r"(r[3]) : "r"(addr));
}
__device__ __forceinline__ void mma16816(float* d, const uint32_t* a, uint32_t b0, uint32_t b1) {
    asm volatile("mma.sync.aligned.m16n8k16.row.col.f32.f16.f16.f32 "
                 "{%0,%1,%2,%3}, {%4,%5,%6,%7}, {%8,%9}, {%0,%1,%2,%3};"
                 : "+f"(d[0]), "+f"(d[1]), "+f"(d[2]), "+f"(d[3])
                 : "r"(a[0]), "r"(a[1]), "r"(a[2]), "r"(a[3]), "r"(b0), "r"(b1));
}

// ===================== phase 1: pure Sinkhorn (128 CTAs x 256 thr) =====================
__device__ __forceinline__ void grid_barrier_s(unsigned* tgt) {
    __syncthreads();
    if (threadIdx.x == 0) {
        __threadfence();
        atomicAdd(&g_bar, 1u);
        const unsigned t = *tgt;
        while (*((const volatile unsigned*)&g_bar) < t) { __nanosleep(32); }
        __threadfence();
    }
    __syncthreads();
    *tgt += NCTA_S;
}

__global__ void __launch_bounds__(STHR)
sinkhorn_kernel(const float* __restrict__ log_scores) {
    __shared__ float rows[RPC][DIMD];   // 32 KB
    __shared__ float cs_s[DIMD];        // 4 KB
    const int tid  = threadIdx.x;
    const int warp = tid >> 5;          // 8 warps = 8 rows
    const int lane = tid & 31;
    const int cta  = blockIdx.x;
    const int rbase = cta * RPC;

    // zero colSum (visibility covered by barrier 0)
    for (int i = cta * STHR + tid; i < NITERS * DIMD; i += NCTA_S * STHR)
        (&g_colSum[0][0])[i] = 0.f;

    // load rows, go to probability domain (TAU = 1)
    for (int i = tid; i < RPC * DIMD; i += STHR)
        rows[i >> 10][i & 1023] = __expf(log_scores[(size_t)rbase * DIMD + i]);

    unsigned tgt = NCTA_S;
    grid_barrier_s(&tgt);

    for (int iter = 0; iter < NITERS; ++iter) {
        if (iter > 0) {
            #pragma unroll
            for (int c = tid; c < DIMD; c += STHR)
                cs_s[c] = __frcp_rn(g_colSum[iter - 1][c]);
            __syncthreads();
        }

        // row normalize: warp w owns row w (fold pending column division)
        {
            float v[32];
            float s = 0.f;
            #pragma unroll
            for (int j = 0; j < 32; ++j) {
                const int col = lane + j * 32;
                float x = rows[warp][col];
                if (iter > 0) x *= cs_s[col];
                v[j] = x;
                s += x;
            }
            #pragma unroll
            for (int o = 16; o; o >>= 1) s += __shfl_xor_sync(0xFFFFFFFFu, s, o);
            const float inv = __frcp_rn(s);
            #pragma unroll
            for (int j = 0; j < 32; ++j) rows[warp][lane + j * 32] = v[j] * inv;
        }
        __syncthreads();

        // column partial over this CTA's 8 rows -> one atomic per column
        #pragma unroll
        for (int c = 0; c < DIMD / STHR; ++c) {
            const int col = tid + c * STHR;
            float p = 0.f;
            #pragma unroll
            for (int r = 0; r < RPC; ++r) p += rows[r][col];
            atomicAdd(&g_colSum[iter][col], p);
        }

        grid_barrier_s(&tgt);
    }

    // final: apply last column normalization, emit P as fp16 (K-major B operand)
    #pragma unroll
    for (int c = tid; c < DIMD; c += STHR)
        cs_s[c] = __frcp_rn(g_colSum[NITERS - 1][c]);
    __syncthreads();
    for (int i = tid; i < RPC * DIMD; i += STHR) {
        const int r = i >> 10, col = i & 1023;
        g_P[(size_t)(rbase + r) * DIMD + col] = __float2half(rows[r][col] * cs_s[col]);
    }

    // reset barrier counters for the next graph replay
    __syncthreads();
    if (tid == 0) {
        __threadfence();
        atomicAdd(&g_done, 1u);
        if (blockIdx.x == 0) {
            while (*((const volatile unsigned*)&g_done) < NCTA_S) { }
            g_bar = 0u;
            g_done = 0u;
            __threadfence();
        }
    }
}

// ===================== GEMM: out = emb @ P^T with fused fp32->fp16 A conversion =====================
// CTA tile 128x128, 4 warps (2x2), warp tile 64x64. K split into 32 stages of K=32.
// Per stage: cp.async lands fp32 A (16KB, 3-deep ring) + fp16 B (8KB, 3-deep ring);
// fp32->fp16 convert of stage s+1 (LDS.128 -> F2FP -> STS.128, 64B-row swizzled fp16
// double buffer) overlaps the 64 HMMAs of stage s. ldsm consumes the fp16 tile.
#define KSTAGES 32
#define F32A_OFF(b) ((b) * 16384)            // 3 x 16KB fp32 A staging
#define F16A_OFF(b) (49152 + (b) * 8192)     // 2 x 8KB fp16 A tiles
#define BB_OFF(b)   (65536 + (b) * 8192)     // 3 x 8KB fp16 B tiles
#define GSMEM_BYTES 90112                    // 88KB/CTA -> 2 CTA/SM

__global__ void __launch_bounds__(128, 2)
gemm_kernel(const float* __restrict__ embA, float* __restrict__ out) {
    extern __shared__ __align__(1024) char smem[];
    const uint32_t sb = smem_to_u32(smem);
    const int tid  = threadIdx.x;
    const int wid  = tid >> 5;
    const int lane = tid & 31;

    // ntile fast-moving -> 8 consecutive CTAs share one A row-block (L2 reuse of A)
    const int ntile = blockIdx.x & 7;
    const int mtile = blockIdx.x >> 3;
    const int m0 = mtile * 128;
    const int n0 = ntile * 128;

    const float*  Ag = embA + (size_t)m0 * DIMD;
    const __half* Bg = g_P  + (size_t)n0 * DIMD;

    // ---- stage issue: fp32 A (8 x 16B/thread) + fp16 B (4 x 16B/thread) ----
#define ISSUE_STAGE(st, buf)                                                        \
    {                                                                               \
        const float*  asrc = Ag + (st) * 32;                                        \
        const __half* bsrc = Bg + (st) * 32;                                        \
        const uint32_t abase = sb + F32A_OFF(buf);                                  \
        const uint32_t bbase = sb + BB_OFF(buf);                                    \
        _Pragma("unroll")                                                           \
        for (int i = 0; i < 8; ++i) {                                               \
            const int idx = tid + i * 128;                                          \
            const int r = idx >> 3, c = idx & 7;                                    \
            const uint32_t sw = (uint32_t)(r * 128 + ((c * 16) ^ ((r & 7) << 4)));  \
            CP_ASYNC16(abase + sw, asrc + (size_t)r * DIMD + c * 4);                \
        }                                                                           \
        _Pragma("unroll")                                                           \
        for (int i = 0; i < 4; ++i) {                                               \
            const int idx = tid + i * 128;                                          \
            const int r = idx >> 2, c = idx & 3;                                    \
            const uint32_t sw = (uint32_t)(r * 64 + ((c * 16) ^ ((r & 3) << 4)));   \
            CP_ASYNC16(bbase + sw, bsrc + (size_t)r * DIMD + c * 8);                \
        }                                                                           \
        CP_ASYNC_COMMIT();                                                          \
    }

    // ---- convert stage: fp32 staging buf -> fp16 tile buf (thread t owns row t) ----
#define CONVERT_STAGE(f32buf, f16buf)                                               \
    {                                                                               \
        const char* sA = smem + F32A_OFF(f32buf) + tid * 128;                       \
        char*       dA = smem + F16A_OFF(f16buf) + tid * 64;                        \
        const uint32_t asw = (uint32_t)((tid & 7) << 4);                            \
        const uint32_t dsw = (uint32_t)((tid & 3) << 4);                            \
        _Pragma("unroll")                                                           \
        for (int i = 0; i < 4; ++i) {                                               \
            const float4 v0 = *reinterpret_cast<const float4*>(sA + (((2*i  )*16) ^ asw)); \
            const float4 v1 = *reinterpret_cast<const float4*>(sA + (((2*i+1)*16) ^ asw)); \
            __half2 h0 = __floats2half2_rn(v0.x, v0.y);                             \
            __half2 h1 = __floats2half2_rn(v0.z, v0.w);                             \
            __half2 h2 = __floats2half2_rn(v1.x, v1.y);                             \
            __half2 h3 = __floats2half2_rn(v1.z, v1.w);                             \
            uint4 o;                                                                \
            o.x = *reinterpret_cast<uint32_t*>(&h0);                                \
            o.y = *reinterpret_cast<uint32_t*>(&h1);                                \
            o.z = *reinterpret_cast<uint32_t*>(&h2);                                \
            o.w = *reinterpret_cast<uint32_t*>(&h3);                                \
            *reinterpret_cast<uint4*>(dA + ((i * 16) ^ dsw)) = o;                   \
        }                                                                           \
    }

    const int warp_m = wid >> 1;   // 0..1
    const int warp_n = wid & 1;    // 0..1

    // ldsm addressing: fp16 rows are 64B, swizzle XOR (row&3)<<4
    int a_pre[4], a_sw[4];
    {
        const int rr = ((lane >> 3) & 1) * 8 + (lane & 7);
        #pragma unroll
        for (int mt = 0; mt < 4; ++mt) {
            const int row = warp_m * 64 + mt * 16 + rr;
            a_pre[mt] = row * 64;
            a_sw[mt]  = (row & 3) << 4;
        }
    }
    const int a_k16 = ((lane >> 4) & 1) * 16;

    int b_pre[4], b_sw[4];
    {
        const int rr = ((lane >> 4) & 1) * 8 + (lane & 7);
        #pragma unroll
        for (int np = 0; np < 4; ++np) {
            const int row = warp_n * 64 + np * 16 + rr;
            b_pre[np] = row * 64;
            b_sw[np]  = (row & 3) << 4;
        }
    }
    const int b_k16 = ((lane >> 3) & 1) * 16;

    float acc[4][8][4];
    #pragma unroll
    for (int mt = 0; mt < 4; ++mt)
        #pragma unroll
        for (int nt = 0; nt < 8; ++nt)
            #pragma unroll
            for (int j = 0; j < 4; ++j) acc[mt][nt][j] = 0.f;

    // prologue: stages 0,1 in flight; convert stage 0 once (exposed ~0.1us)
    ISSUE_STAGE(0, 0);
    ISSUE_STAGE(1, 1);
    CP_ASYNC_WAIT1();          // group 0 arrived
    __syncthreads();
    CONVERT_STAGE(0, 0);

    for (int s = 0; s < KSTAGES; ++s) {
        if (s + 2 < KSTAGES) { ISSUE_STAGE(s + 2, (s + 2) % 3); }
        else                 { CP_ASYNC_COMMIT(); }
        CP_ASYNC_WAIT1();      // stage s+1's fp32/B arrived (and s's, transitively)
        __syncthreads();       // also: fp16[(s+1)&1] free (consumed at s-1), staging ring safe

        // convert next stage (overlaps with this stage's MMAs)
        if (s + 1 < KSTAGES) CONVERT_STAGE((s + 1) % 3, (s + 1) & 1);

        const uint32_t Ab = sb + F16A_OFF(s & 1);
        const uint32_t Bb = sb + BB_OFF(s % 3);
        #pragma unroll
        for (int ks = 0; ks < 2; ++ks) {
            const int kb = ks * 32;
            uint32_t av[4][4];
            #pragma unroll
            for (int mt = 0; mt < 4; ++mt)
                ldsm_x4(av[mt], Ab + a_pre[mt] + ((kb | a_k16) ^ a_sw[mt]));
            uint32_t bv[4][4];
            #pragma unroll
            for (int np = 0; np < 4; ++np)
                ldsm_x4(bv[np], Bb + b_pre[np] + ((kb | b_k16) ^ b_sw[np]));
            #pragma unroll
            for (int mt = 0; mt < 4; ++mt)
                #pragma unroll
                for (int np = 0; np < 4; ++np) {
                    mma16816(acc[mt][2 * np + 0], av[mt], bv[np][0], bv[np][1]);
                    mma16816(acc[mt][2 * np + 1], av[mt], bv[np][2], bv[np][3]);
                }
        }
    }
#undef ISSUE_STAGE
#undef CONVERT_STAGE

    // epilogue: direct coalesced STG.64
    const int r0c = lane >> 2;
    const int c0c = (lane & 3) * 2;
    #pragma unroll
    for (int mt = 0; mt < 4; ++mt) {
        const int row_base = m0 + warp_m * 64 + mt * 16 + r0c;
        #pragma unroll
        for (int nt = 0; nt < 8; ++nt) {
            const int col = n0 + warp_n * 64 + nt * 8 + c0c;
            float2 v0 = make_float2(acc[mt][nt][0], acc[mt][nt][1]);
            float2 v1 = make_float2(acc[mt][nt][2], acc[mt][nt][3]);
            *reinterpret_cast<float2*>(out + (size_t)row_base * DIMD + col)       = v0;
            *reinterpret_cast<float2*>(out + (size_t)(row_base + 8) * DIMD + col) = v1;
        }
    }
}

// ===================== launch =====================
extern "C" void kernel_launch(void* const* d_in, const int* in_sizes, int n_in,
                              void* d_out, int out_size) {
    const float* emb;
    const float* ls;
    if (n_in >= 2 && in_sizes[0] == DIMD * DIMD && in_sizes[1] != DIMD * DIMD) {
        ls  = (const float*)d_in[0];
        emb = (const float*)d_in[1];
    } else {
        emb = (const float*)d_in[0];
        ls  = (const float*)d_in[1];
    }
    float* out = (float*)d_out;

    static bool attr_done = false;
    if (!attr_done) {
        cudaFuncSetAttribute(gemm_kernel, cudaFuncAttributeMaxDynamicSharedMemorySize, GSMEM_BYTES);
        attr_done = true;
    }

    // serial, deterministic: sinkhorn -> fused-convert GEMM (no cvt pass, no streams)
    sinkhorn_kernel<<<NCTA_S, STHR>>>(ls);
    gemm_kernel<<<(BATCH / 128) * (DIMD / 128), 128, GSMEM_BYTES>>>(emb, out);
}

// round 13
// speedup vs baseline: 1.2131x; 1.2131x over previous
#include <cuda_runtime.h>
#include <cuda_fp16.h>
#include <cstdint>

// ===================== problem constants =====================
#define DIMD 1024
#define BATCH 65536
#define NITERS 20

// sinkhorn config: 32 CTAs x 1024 threads, 32 rows/CTA (warp-per-row)
#define NCTA_S 32
#define STHR 1024
#define RPC 32
#define SINK_SMEM ((RPC * DIMD + DIMD) * 4)   // rows[32][1024] + cs[1024] = 132 KB

// ===================== device globals (static scratch; never allocated) =====================
__device__ __half  g_P[DIMD * DIMD];            // Sinkhorn P (row-major = K-major B operand)
__device__ __half  g_A16[(size_t)BATCH * DIMD]; // fp16 embeddings (cvt prepass output)
__device__ float   g_colSum[NITERS][DIMD];      // per-iter column sums (RED-accumulated)
__device__ unsigned g_bar;                      // monotonic grid barrier counter
__device__ unsigned g_done;                     // end-of-kernel reset rendezvous

// ===================== small PTX helpers (plain sm_103-legal only) =====================
__device__ __forceinline__ uint32_t smem_to_u32(const void* p) {
    uint32_t a;
    asm("{ .reg .u64 t; cvta.to.shared.u64 t, %1; cvt.u32.u64 %0, t; }" : "=r"(a) : "l"(p));
    return a;
}

#define CP_ASYNC16(dst, src) \
    asm volatile("cp.async.cg.shared.global [%0], [%1], 16;" :: "r"(dst), "l"(src) : "memory")
#define CP_ASYNC_COMMIT() asm volatile("cp.async.commit_group;" ::: "memory")
#define CP_ASYNC_WAIT1()  asm volatile("cp.async.wait_group 1;" ::: "memory")

__device__ __forceinline__ void ldsm_x4(uint32_t* r, uint32_t addr) {
    asm volatile("ldmatrix.sync.aligned.m8n8.x4.shared.b16 {%0,%1,%2,%3}, [%4];"
                 : "=r"(r[0]), "=r"(r[1]), "=r"(r[2]), "=r"(r[3]) : "r"(addr));
}
__device__ __forceinline__ void mma16816(float* d, const uint32_t* a, uint32_t b0, uint32_t b1) {
    asm volatile("mma.sync.aligned.m16n8k16.row.col.f32.f16.f16.f32 "
                 "{%0,%1,%2,%3}, {%4,%5,%6,%7}, {%8,%9}, {%0,%1,%2,%3};"
                 : "+f"(d[0]), "+f"(d[1]), "+f"(d[2]), "+f"(d[3])
                 : "r"(a[0]), "r"(a[1]), "r"(a[2]), "r"(a[3]), "r"(b0), "r"(b1));
}

// ===================== phase 1: Sinkhorn, 32 CTAs x 1024 thr (low-latency barrier) =====================
__device__ __forceinline__ void grid_barrier_s(unsigned* tgt) {
    __syncthreads();
    if (threadIdx.x == 0) {
        __threadfence();
        atomicAdd(&g_bar, 1u);
        const unsigned t = *tgt;
        while (*((const volatile unsigned*)&g_bar) < t) { __nanosleep(32); }
        __threadfence();
    }
    __syncthreads();
    *tgt += NCTA_S;
}

__global__ void __launch_bounds__(STHR)
sinkhorn_kernel(const float* __restrict__ log_scores) {
    extern __shared__ __align__(16) float smem_s[];
    float* rows = smem_s;                 // [RPC][DIMD] = 128 KB
    float* cs   = smem_s + RPC * DIMD;    // [DIMD]      = 4 KB
    const int tid  = threadIdx.x;
    const int warp = tid >> 5;            // 32 warps = 32 rows
    const int lane = tid & 31;
    const int cta  = blockIdx.x;
    const int rbase = cta * RPC;

    // zero colSum (20480 elems over 32768 threads; visibility via barrier 0)
    {
        const int i = cta * STHR + tid;
        if (i < NITERS * DIMD) (&g_colSum[0][0])[i] = 0.f;
    }

    // load rows, go to probability domain (TAU = 1)
    for (int i = tid; i < RPC * DIMD; i += STHR)
        rows[i] = __expf(log_scores[(size_t)rbase * DIMD + i]);

    unsigned tgt = NCTA_S;
    grid_barrier_s(&tgt);

    for (int iter = 0; iter < NITERS; ++iter) {
        if (iter > 0) {
            cs[tid] = __frcp_rn(g_colSum[iter - 1][tid]);
            __syncthreads();
        }

        // row normalize: warp w owns row w (fold pending column division)
        {
            float v[32];
            float s = 0.f;
            float* rw = rows + warp * DIMD;
            #pragma unroll
            for (int j = 0; j < 32; ++j) {
                const int col = lane + j * 32;
                float x = rw[col];
                if (iter > 0) x *= cs[col];
                v[j] = x;
                s += x;
            }
            #pragma unroll
            for (int o = 16; o; o >>= 1) s += __shfl_xor_sync(0xFFFFFFFFu, s, o);
            const float inv = __frcp_rn(s);
            #pragma unroll
            for (int j = 0; j < 32; ++j) rw[lane + j * 32] = v[j] * inv;
        }
        __syncthreads();

        // column partial over this CTA's 32 rows -> one RED per column (col = tid)
        {
            float p = 0.f;
            #pragma unroll
            for (int r = 0; r < RPC; ++r) p += rows[r * DIMD + tid];
            atomicAdd(&g_colSum[iter][tid], p);   // return unused -> REDG
        }

        grid_barrier_s(&tgt);
    }

    // final: apply last column normalization, emit P as fp16 (K-major B operand)
    cs[tid] = __frcp_rn(g_colSum[NITERS - 1][tid]);
    __syncthreads();
    for (int i = tid; i < RPC * DIMD; i += STHR) {
        const int col = i & 1023;
        g_P[(size_t)rbase * DIMD + i] = __float2half(rows[i] * cs[col]);
    }

    // reset barrier counters for the next graph replay
    __syncthreads();
    if (tid == 0) {
        __threadfence();
        atomicAdd(&g_done, 1u);
        if (blockIdx.x == 0) {
            while (*((const volatile unsigned*)&g_done) < NCTA_S) { }
            g_bar = 0u;
            g_done = 0u;
            __threadfence();
        }
    }
}

// ===================== phase 2: fp32 -> fp16 embeddings prepass =====================
#define N4 16777216         // BATCH/4 * DIMD float4 elements
__global__ void __launch_bounds__(256)
cvt_kernel(const float4* __restrict__ A) {
    uint2* dst = reinterpret_cast<uint2*>(g_A16);
    for (int i = blockIdx.x * 256 + threadIdx.x; i < N4; i += gridDim.x * 256) {
        const float4 v = A[i];
        __half2 h0 = __floats2half2_rn(v.x, v.y);
        __half2 h1 = __floats2half2_rn(v.z, v.w);
        dst[i] = make_uint2(*reinterpret_cast<const uint32_t*>(&h0),
                            *reinterpret_cast<const uint32_t*>(&h1));
    }
}

// ===================== phase 3: GEMM out = A16 @ P^T (R5-proven mainloop) =====================
// CTA tile 128x128, 4 warps (2x2), warp tile 64x64, K-stage 64 (16 stages), 3-stage cp.async.
#define KSTAGES 16
#define STAGE_BYTES 16384
#define B_BASE (3 * STAGE_BYTES)
#define GSMEM_BYTES (6 * STAGE_BYTES)

__global__ void __launch_bounds__(128, 2)
gemm_kernel(float* __restrict__ out) {
    extern __shared__ __align__(1024) char smem[];
    const uint32_t sb = smem_to_u32(smem);
    const int tid  = threadIdx.x;
    const int wid  = tid >> 5;
    const int lane = tid & 31;

    // ntile fast-moving -> 8 consecutive CTAs share one A row-block (L2 reuse of A)
    const int ntile = blockIdx.x & 7;
    const int mtile = blockIdx.x >> 3;
    const int m0 = mtile * 128;
    const int n0 = ntile * 128;

    const __half* Ag = g_A16 + (size_t)m0 * DIMD;
    const __half* Bg = g_P   + (size_t)n0 * DIMD;

#define ISSUE_STAGE(st, buf)                                                     \
    {                                                                            \
        const __half* asrc = Ag + (st) * 64;                                     \
        const __half* bsrc = Bg + (st) * 64;                                     \
        const uint32_t abase = sb + (buf) * STAGE_BYTES;                         \
        const uint32_t bbase = sb + B_BASE + (buf) * STAGE_BYTES;                \
        _Pragma("unroll")                                                        \
        for (int i = 0; i < 8; ++i) {                                            \
            const int idx = tid + i * 128;                                       \
            const int r = idx >> 3, c = idx & 7;                                 \
            const uint32_t sw = (uint32_t)(r * 128 + ((c * 16) ^ ((r & 7) << 4)));\
            CP_ASYNC16(abase + sw, asrc + (size_t)r * DIMD + c * 8);             \
            CP_ASYNC16(bbase + sw, bsrc + (size_t)r * DIMD + c * 8);             \
        }                                                                        \
        CP_ASYNC_COMMIT();                                                       \
    }

    const int warp_m = wid >> 1;   // 0..1
    const int warp_n = wid & 1;    // 0..1

    int a_pre[4], a_sw[4];
    {
        const int rr = ((lane >> 3) & 1) * 8 + (lane & 7);
        #pragma unroll
        for (int mt = 0; mt < 4; ++mt) {
            const int row = warp_m * 64 + mt * 16 + rr;
            a_pre[mt] = row * 128;
            a_sw[mt]  = (row & 7) << 4;
        }
    }
    const int a_k16 = ((lane >> 4) & 1) * 16;

    int b_pre[4], b_sw[4];
    {
        const int rr = ((lane >> 4) & 1) * 8 + (lane & 7);
        #pragma unroll
        for (int np = 0; np < 4; ++np) {
            const int row = warp_n * 64 + np * 16 + rr;
            b_pre[np] = row * 128;
            b_sw[np]  = (row & 7) << 4;
        }
    }
    const int b_k16 = ((lane >> 3) & 1) * 16;

    float acc[4][8][4];
    #pragma unroll
    for (int mt = 0; mt < 4; ++mt)
        #pragma unroll
        for (int nt = 0; nt < 8; ++nt)
            #pragma unroll
            for (int j = 0; j < 4; ++j) acc[mt][nt][j] = 0.f;

    ISSUE_STAGE(0, 0);
    ISSUE_STAGE(1, 1);

    for (int s = 0; s < KSTAGES; ++s) {
        const int buf = s % 3;
        CP_ASYNC_WAIT1();
        __syncthreads();
        if (s + 2 < KSTAGES) { ISSUE_STAGE(s + 2, (s + 2) % 3); }
        else                 { CP_ASYNC_COMMIT(); }

        const uint32_t Ab = sb + buf * STAGE_BYTES;
        const uint32_t Bb = sb + B_BASE + buf * STAGE_BYTES;
        #pragma unroll
        for (int ks = 0; ks < 4; ++ks) {
            const int kb = ks * 32;
            uint32_t av[4][4];
            #pragma unroll
            for (int mt = 0; mt < 4; ++mt)
                ldsm_x4(av[mt], Ab + a_pre[mt] + ((kb | a_k16) ^ a_sw[mt]));
            uint32_t bv[4][4];
            #pragma unroll
            for (int np = 0; np < 4; ++np)
                ldsm_x4(bv[np], Bb + b_pre[np] + ((kb | b_k16) ^ b_sw[np]));
            #pragma unroll
            for (int mt = 0; mt < 4; ++mt)
                #pragma unroll
                for (int np = 0; np < 4; ++np) {
                    mma16816(acc[mt][2 * np + 0], av[mt], bv[np][0], bv[np][1]);
                    mma16816(acc[mt][2 * np + 1], av[mt], bv[np][2], bv[np][3]);
                }
        }
    }
#undef ISSUE_STAGE

    // epilogue: direct coalesced STG.64
    const int r0c = lane >> 2;
    const int c0c = (lane & 3) * 2;
    #pragma unroll
    for (int mt = 0; mt < 4; ++mt) {
        const int row_base = m0 + warp_m * 64 + mt * 16 + r0c;
        #pragma unroll
        for (int nt = 0; nt < 8; ++nt) {
            const int col = n0 + warp_n * 64 + nt * 8 + c0c;
            float2 v0 = make_float2(acc[mt][nt][0], acc[mt][nt][1]);
            float2 v1 = make_float2(acc[mt][nt][2], acc[mt][nt][3]);
            *reinterpret_cast<float2*>(out + (size_t)row_base * DIMD + col)       = v0;
            *reinterpret_cast<float2*>(out + (size_t)(row_base + 8) * DIMD + col) = v1;
        }
    }
}

// ===================== launch =====================
extern "C" void kernel_launch(void* const* d_in, const int* in_sizes, int n_in,
                              void* d_out, int out_size) {
    const float* emb;
    const float* ls;
    if (n_in >= 2 && in_sizes[0] == DIMD * DIMD && in_sizes[1] != DIMD * DIMD) {
        ls  = (const float*)d_in[0];
        emb = (const float*)d_in[1];
    } else {
        emb = (const float*)d_in[0];
        ls  = (const float*)d_in[1];
    }
    float* out = (float*)d_out;

    static bool attr_done = false;
    if (!attr_done) {
        cudaFuncSetAttribute(sinkhorn_kernel, cudaFuncAttributeMaxDynamicSharedMemorySize, SINK_SMEM);
        cudaFuncSetAttribute(gemm_kernel, cudaFuncAttributeMaxDynamicSharedMemorySize, GSMEM_BYTES);
        attr_done = true;
    }

    // serial, deterministic: sinkhorn (low-latency 32-CTA barrier) -> cvt -> GEMM
    sinkhorn_kernel<<<NCTA_S, STHR, SINK_SMEM>>>(ls);
    cvt_kernel<<<2048, 256>>>(reinterpret_cast<const float4*>(emb));
    gemm_kernel<<<(BATCH / 128) * (DIMD / 128), 128, GSMEM_BYTES>>>(out);
}